// round 10
// baseline (speedup 1.0000x reference)
#include <cuda_runtime.h>
#include <cuda_fp16.h>
#include <math.h>
#include <stdint.h>

#define N_TOK 4096
#define EMB   1024

typedef __half fp16;

// ---------------------------------------------------------------------------
// Device scratch (alloc-free rule: __device__ globals)
// ---------------------------------------------------------------------------
__device__ __align__(256) fp16 gXs0[(size_t)N_TOK * EMB];   // X limbs row-major [4096,1024]
__device__ __align__(256) fp16 gXs1[(size_t)N_TOK * EMB];
__device__ __align__(256) fp16 gXT0[(size_t)EMB * N_TOK];   // X^T limbs [1024,4096]
__device__ __align__(256) fp16 gXT1[(size_t)EMB * N_TOK];
__device__ __align__(256) fp16 gWqs0[(size_t)EMB * EMB];    // Wq limbs row-major
__device__ __align__(256) fp16 gWqs1[(size_t)EMB * EMB];
__device__ __align__(256) fp16 gWks0[(size_t)EMB * EMB];    // Wk limbs row-major
__device__ __align__(256) fp16 gWks1[(size_t)EMB * EMB];
__device__ __align__(256) fp16 gMT0[(size_t)EMB * EMB];     // M^T = Wk Wq^T limbs
__device__ __align__(256) fp16 gMT1[(size_t)EMB * EMB];
__device__ __align__(256) fp16 gT0[(size_t)N_TOK * EMB];    // T = X M limbs
__device__ __align__(256) fp16 gT1[(size_t)N_TOK * EMB];
__device__ __align__(256) float gS[(size_t)N_TOK * N_TOK];  // scaled logits
__device__ __align__(256) fp16 gSh[(size_t)N_TOK * N_TOK];  // softmax probs (1 limb)

// ---------------------------------------------------------------------------
// helpers
// ---------------------------------------------------------------------------
__device__ __forceinline__ uint32_t smem_u32(const void* p) {
    return (uint32_t)__cvta_generic_to_shared(p);
}
__device__ __forceinline__ void cp16(uint32_t dst, const void* src) {
    asm volatile("cp.async.cg.shared.global [%0], [%1], 16;" :: "r"(dst), "l"(src));
}
__device__ __forceinline__ void cp_commit() { asm volatile("cp.async.commit_group;" ::: "memory"); }
__device__ __forceinline__ void cp_wait1()  { asm volatile("cp.async.wait_group 1;" ::: "memory"); }

__device__ __forceinline__ void ldsm_x4(uint32_t* r, uint32_t addr) {
    asm volatile("ldmatrix.sync.aligned.m8n8.x4.shared.b16 {%0,%1,%2,%3}, [%4];"
                 : "=r"(r[0]), "=r"(r[1]), "=r"(r[2]), "=r"(r[3]) : "r"(addr));
}

__device__ __forceinline__ void mma16816(float* d, const uint32_t* a, const uint32_t* b) {
    asm volatile(
        "mma.sync.aligned.m16n8k16.row.col.f32.f16.f16.f32 "
        "{%0,%1,%2,%3}, {%4,%5,%6,%7}, {%8,%9}, {%0,%1,%2,%3};"
        : "+f"(d[0]), "+f"(d[1]), "+f"(d[2]), "+f"(d[3])
        : "r"(a[0]), "r"(a[1]), "r"(a[2]), "r"(a[3]), "r"(b[0]), "r"(b[1]));
}

// fp16-accumulator variant (cross terms only; D = 2 x .f16x2 regs)
__device__ __forceinline__ void mma16816_f16(uint32_t* d, const uint32_t* a, const uint32_t* b) {
    asm volatile(
        "mma.sync.aligned.m16n8k16.row.col.f16.f16.f16.f16 "
        "{%0,%1}, {%2,%3,%4,%5}, {%6,%7}, {%0,%1};"
        : "+r"(d[0]), "+r"(d[1])
        : "r"(a[0]), "r"(a[1]), "r"(a[2]), "r"(a[3]), "r"(b[0]), "r"(b[1]));
}

__device__ __forceinline__ void split2(float v, fp16& h, fp16& l) {
    h = __float2half_rn(v);
    l = __float2half_rn(v - __half2float(h));
}

// swizzled addr inside a 128row x 128B tile: row r, 16B-chunk c (0..7)
__device__ __forceinline__ uint32_t sw_addr(uint32_t base, int r, int c) {
    return base + r * 128 + (((uint32_t)(c ^ (r & 7))) << 4);
}

// ---------------------------------------------------------------------------
// Tile loader: NL limbs, 128 rows x 64 fp16 (128B rows, swizzled), 16KB each
// ---------------------------------------------------------------------------
template <int NL>
__device__ __forceinline__ void load_tiles(const fp16* p0, const fp16* p1,
                                           uint32_t base, int row0, int K, int k0, int tid)
{
    const fp16* ps[2] = { p0, p1 };
#pragma unroll
    for (int s = 0; s < NL; s++) {
#pragma unroll
        for (int i = 0; i < 4; i++) {
            int idx = i * 256 + tid;         // 0..1023
            int r = idx >> 3;                // row 0..127
            int c = idx & 7;                 // 16B chunk 0..7
            const fp16* src = ps[s] + (size_t)(row0 + r) * K + k0 + c * 8;
            cp16(sw_addr(base + s * 16384, r, c), src);
        }
    }
}

// ---------------------------------------------------------------------------
// fp16 limb-product split-GEMM (frozen R6 shell; dedup'd inner loop).
// Products (grouped to avoid fragment reloads):
//   A0.B0 (fp32 acc)  [always]
//   A0.B1 (fp32 acc, or shared fp16 acc if CROSS16)  [NPROD>=2]
//   A1.B0 (fp32 acc, or shared fp16 acc if CROSS16)  [NPROD==3]
// CTA tile 128x128, KC=64. 8 warps: warp_m = wid&1 (64 rows), warp_n = wid>>1.
// EPI 0: fp32 store to Cf.  EPI 1: 2-limb fp16 split store to C0/C1.
// ---------------------------------------------------------------------------
template <int NLA, int NLB, int NPROD, int CROSS16, int EPI>
__global__ __launch_bounds__(256, 1)
void hgemm_kernel(const fp16* __restrict__ A0, const fp16* __restrict__ A1,
                  const fp16* __restrict__ B0, const fp16* __restrict__ B1,
                  float* __restrict__ Cf, fp16* __restrict__ C0, fp16* __restrict__ C1,
                  int K, int KITERS, int ldc, float alpha)
{
    constexpr int STAGE_BYTES = (NLA + NLB) * 16384;
    extern __shared__ char smem[];
    const uint32_t SBASE = smem_u32(smem);   // 2 stages x (NLA+NLB) x 16KB

    const int tid = threadIdx.x;
    const int wid = tid >> 5;
    const int lid = tid & 31;
    const int m0 = blockIdx.y * 128;
    const int n0 = blockIdx.x * 128;
    const int m0w = (wid & 1) * 64;
    const int n0w = (wid >> 1) * 32;

    float acc[4][4][4];
#pragma unroll
    for (int i = 0; i < 4; i++)
#pragma unroll
        for (int j = 0; j < 4; j++)
#pragma unroll
            for (int k = 0; k < 4; k++) acc[i][j][k] = 0.f;

    uint32_t acc16[4][4][2];
    if (CROSS16) {
#pragma unroll
        for (int i = 0; i < 4; i++)
#pragma unroll
            for (int j = 0; j < 4; j++) { acc16[i][j][0] = 0u; acc16[i][j][1] = 0u; }
    }

    const int sel = lid >> 3;
    const int lrow = lid & 7;
    const int a_rb = (sel & 1) * 8;   // A x4: M0=(r0,k0) M1=(r1,k0) M2=(r0,k1) M3=(r1,k1)
    const int a_kb = sel >> 1;
    const int b_nb = (sel >> 1) * 8;  // B x4: M0=(n0,k0) M1=(n0,k1) M2=(n1,k0) M3=(n1,k1)
    const int b_kb = sel & 1;

    // prologue: stages 0,1
    load_tiles<NLA>(A0, A1, SBASE, m0, K, 0, tid);
    load_tiles<NLB>(B0, B1, SBASE + NLA * 16384, n0, K, 0, tid);
    cp_commit();
    load_tiles<NLA>(A0, A1, SBASE + STAGE_BYTES, m0, K, 64, tid);
    load_tiles<NLB>(B0, B1, SBASE + STAGE_BYTES + NLA * 16384, n0, K, 64, tid);
    cp_commit();

    for (int it = 0; it < KITERS; it++) {
        const int stage = it & 1;
        cp_wait1();
        __syncthreads();

        const uint32_t abase_st = SBASE + stage * STAGE_BYTES;
        const uint32_t bbase_st = abase_st + NLA * 16384;

#pragma unroll
        for (int ks = 0; ks < 4; ks++) {
            // A0 fragments
            uint32_t afr0[4][4];
#pragma unroll
            for (int mt = 0; mt < 4; mt++)
                ldsm_x4(afr0[mt], sw_addr(abase_st, m0w + mt * 16 + a_rb + lrow, ks * 2 + a_kb));
            // B0 fragments
            uint32_t bfr0[2][4];
#pragma unroll
            for (int j = 0; j < 2; j++)
                ldsm_x4(bfr0[j], sw_addr(bbase_st, n0w + j * 16 + b_nb + lrow, ks * 2 + b_kb));
            // main product A0.B0 -> fp32
#pragma unroll
            for (int mt = 0; mt < 4; mt++)
#pragma unroll
                for (int nt = 0; nt < 4; nt++)
                    mma16816(acc[mt][nt], afr0[mt], &bfr0[nt >> 1][(nt & 1) * 2]);

            if (NPROD >= 2) {
                // B1 fragments; A0 still live
                uint32_t bfr1[2][4];
#pragma unroll
                for (int j = 0; j < 2; j++)
                    ldsm_x4(bfr1[j], sw_addr(bbase_st + 16384, n0w + j * 16 + b_nb + lrow, ks * 2 + b_kb));
                if (CROSS16) {
#pragma unroll
                    for (int mt = 0; mt < 4; mt++)
#pragma unroll
                        for (int nt = 0; nt < 4; nt++)
                            mma16816_f16(acc16[mt][nt], afr0[mt], &bfr1[nt >> 1][(nt & 1) * 2]);
                } else {
#pragma unroll
                    for (int mt = 0; mt < 4; mt++)
#pragma unroll
                        for (int nt = 0; nt < 4; nt++)
                            mma16816(acc[mt][nt], afr0[mt], &bfr1[nt >> 1][(nt & 1) * 2]);
                }
            }

            if (NPROD == 3) {
                // A1 fragments; B0 still live
                uint32_t afr1[4][4];
#pragma unroll
                for (int mt = 0; mt < 4; mt++)
                    ldsm_x4(afr1[mt], sw_addr(abase_st + 16384, m0w + mt * 16 + a_rb + lrow, ks * 2 + a_kb));
                if (CROSS16) {
#pragma unroll
                    for (int mt = 0; mt < 4; mt++)
#pragma unroll
                        for (int nt = 0; nt < 4; nt++)
                            mma16816_f16(acc16[mt][nt], afr1[mt], &bfr0[nt >> 1][(nt & 1) * 2]);
                } else {
#pragma unroll
                    for (int mt = 0; mt < 4; mt++)
#pragma unroll
                        for (int nt = 0; nt < 4; nt++)
                            mma16816(acc[mt][nt], afr1[mt], &bfr0[nt >> 1][(nt & 1) * 2]);
                }
            }
        }
        __syncthreads();

        if (it + 2 < KITERS) {
            load_tiles<NLA>(A0, A1, abase_st, m0, K, (it + 2) * 64, tid);
            load_tiles<NLB>(B0, B1, bbase_st, n0, K, (it + 2) * 64, tid);
        }
        cp_commit();
    }

    // epilogue: lane l owns rows gr, gr+8 and col pair (l&3)*2 of each 16x8 frag
    const int gr = lid >> 2;
    const int cp = (lid & 3) * 2;
#pragma unroll
    for (int mt = 0; mt < 4; mt++) {
#pragma unroll
        for (int half = 0; half < 2; half++) {
            const int row = m0 + m0w + mt * 16 + gr + half * 8;
#pragma unroll
            for (int nt = 0; nt < 4; nt++) {
                const int col = n0 + n0w + nt * 8 + cp;
                float v0 = acc[mt][nt][half * 2 + 0];
                float v1 = acc[mt][nt][half * 2 + 1];
                if (CROSS16) {
                    __half2 hc = *(__half2*)&acc16[mt][nt][half];
                    v0 += __low2float(hc);
                    v1 += __high2float(hc);
                }
                v0 *= alpha;
                v1 *= alpha;
                size_t off = (size_t)row * ldc + col;
                if (EPI == 0) {
                    *(float2*)&Cf[off] = make_float2(v0, v1);
                } else {
                    fp16 h0, l0, h1, l1;
                    split2(v0, h0, l0);
                    split2(v1, h1, l1);
                    *(__half2*)&C0[off] = __halves2half2(h0, h1);
                    *(__half2*)&C1[off] = __halves2half2(l0, l1);
                }
            }
        }
    }
}

// ---------------------------------------------------------------------------
// Elementwise 2-limb split
// ---------------------------------------------------------------------------
__global__ __launch_bounds__(256)
void split2_kernel(const float* __restrict__ in, fp16* __restrict__ o0,
                   fp16* __restrict__ o1, int n)
{
    for (int i = blockIdx.x * 256 + threadIdx.x; i < n; i += gridDim.x * 256) {
        fp16 h, l;
        split2(in[i], h, l);
        o0[i] = h; o1[i] = l;
    }
}

// ---------------------------------------------------------------------------
// Transposing 2-limb split: in [R,C] fp32 -> out [C,R] limbs
// ---------------------------------------------------------------------------
__global__ __launch_bounds__(256)
void tsplit2_kernel(const float* __restrict__ in, fp16* __restrict__ o0,
                    fp16* __restrict__ o1, int R, int C)
{
    __shared__ float t[32][33];
    const int cb = blockIdx.x * 32, rb = blockIdx.y * 32;
    const int tx = threadIdx.x & 31, ty = threadIdx.x >> 5;
#pragma unroll
    for (int i = 0; i < 32; i += 8)
        t[ty + i][tx] = in[(size_t)(rb + ty + i) * C + cb + tx];
    __syncthreads();
#pragma unroll
    for (int i = 0; i < 32; i += 8) {
        float v = t[tx][ty + i];
        fp16 h, l;
        split2(v, h, l);
        size_t off = (size_t)(cb + ty + i) * R + rb + tx;
        o0[off] = h;
        o1[off] = l;
    }
}

// ---------------------------------------------------------------------------
// Row softmax of scaled logits -> single fp16 limb (probs are near-one-hot)
// ---------------------------------------------------------------------------
__global__ __launch_bounds__(256)
void softmax_kernel(const float* __restrict__ S, fp16* __restrict__ H)
{
    __shared__ float buf[N_TOK];
    __shared__ float red[256];
    const int row = blockIdx.x;
    const int t = threadIdx.x;
    const float* p = S + (size_t)row * N_TOK;

    float m = -INFINITY;
    for (int i = t; i < N_TOK; i += 256) {
        float v = p[i];
        buf[i] = v;
        m = fmaxf(m, v);
    }
    red[t] = m;
    __syncthreads();
    for (int s = 128; s > 0; s >>= 1) {
        if (t < s) red[t] = fmaxf(red[t], red[t + s]);
        __syncthreads();
    }
    m = red[0];
    __syncthreads();

    float sum = 0.f;
    for (int i = t; i < N_TOK; i += 256) {
        float e = __expf(buf[i] - m);
        buf[i] = e;
        sum += e;
    }
    red[t] = sum;
    __syncthreads();
    for (int s = 128; s > 0; s >>= 1) {
        if (t < s) red[t] += red[t + s];
        __syncthreads();
    }
    const float inv = 1.0f / red[0];
    __syncthreads();

    for (int i = t; i < N_TOK; i += 256)
        H[(size_t)row * N_TOK + i] = __float2half_rn(buf[i] * inv);
}

// ---------------------------------------------------------------------------
extern "C" void kernel_launch(void* const* d_in, const int* in_sizes, int n_in,
                              void* d_out, int out_size)
{
    const float* X  = (const float*)d_in[0];
    const float* Wq = (const float*)d_in[1];
    const float* Wk = (const float*)d_in[2];
    float* out      = (float*)d_out;

    fp16 *xs0, *xs1, *xt0, *xt1, *wq0, *wq1, *wk0, *wk1;
    fp16 *mt0, *mt1, *t0, *t1, *sh;
    float* s;
    cudaGetSymbolAddress((void**)&xs0, gXs0); cudaGetSymbolAddress((void**)&xs1, gXs1);
    cudaGetSymbolAddress((void**)&xt0, gXT0); cudaGetSymbolAddress((void**)&xt1, gXT1);
    cudaGetSymbolAddress((void**)&wq0, gWqs0); cudaGetSymbolAddress((void**)&wq1, gWqs1);
    cudaGetSymbolAddress((void**)&wk0, gWks0); cudaGetSymbolAddress((void**)&wk1, gWks1);
    cudaGetSymbolAddress((void**)&mt0, gMT0); cudaGetSymbolAddress((void**)&mt1, gMT1);
    cudaGetSymbolAddress((void**)&t0, gT0); cudaGetSymbolAddress((void**)&t1, gT1);
    cudaGetSymbolAddress((void**)&s, gS);
    cudaGetSymbolAddress((void**)&sh, gSh);

    const int SM22 = 2 * 4 * 16384;  // 2 stages x (2A + 2B limbs) x 16KB = 128KB
    const int SM12 = 2 * 3 * 16384;  // 2 stages x (1A + 2B limbs) x 16KB = 96KB
    cudaFuncSetAttribute(hgemm_kernel<2,2,3,1,0>, cudaFuncAttributeMaxDynamicSharedMemorySize, SM22);
    cudaFuncSetAttribute(hgemm_kernel<2,2,3,0,1>, cudaFuncAttributeMaxDynamicSharedMemorySize, SM22);
    cudaFuncSetAttribute(hgemm_kernel<1,2,2,1,0>, cudaFuncAttributeMaxDynamicSharedMemorySize, SM12);

    // 1) input splits
    split2_kernel<<<2048, 256>>>(X, xs0, xs1, N_TOK * EMB);
    split2_kernel<<<512, 256>>>(Wq, wq0, wq1, EMB * EMB);
    split2_kernel<<<512, 256>>>(Wk, wk0, wk1, EMB * EMB);
    tsplit2_kernel<<<dim3(EMB / 32, N_TOK / 32), 256>>>(X, xt0, xt1, N_TOK, EMB);

    // 2) M^T = Wk @ Wq^T  (split output; full fp32 accum — T precision matters)
    hgemm_kernel<2,2,3,0,1><<<dim3(EMB / 128, EMB / 128), 256, SM22>>>(
        wk0, wk1, wq0, wq1, nullptr, mt0, mt1, EMB, EMB / 64, EMB, 1.0f);

    // 3) T = X @ M  (B = M^T row-major; split output; full fp32 accum)
    hgemm_kernel<2,2,3,0,1><<<dim3(EMB / 128, N_TOK / 128), 256, SM22>>>(
        xs0, xs1, mt0, mt1, nullptr, t0, t1, EMB, EMB / 64, EMB, 1.0f);

    // 4) scaled logits = (T @ X^T) / 32  (cross products -> fp16 accum)
    hgemm_kernel<2,2,3,1,0><<<dim3(N_TOK / 128, N_TOK / 128), 256, SM22>>>(
        t0, t1, xs0, xs1, s, nullptr, nullptr, EMB, EMB / 64, N_TOK, 1.0f / 32.0f);

    // 5) softmax rows -> single fp16 limb
    softmax_kernel<<<N_TOK, 256>>>(s, sh);

    // 6) out = S @ X  (A = Sh 1 limb; B = X^T limbs; main fp32 + cross fp16-accum)
    hgemm_kernel<1,2,2,1,0><<<dim3(EMB / 128, N_TOK / 128), 256, SM12>>>(
        sh, nullptr, xt0, xt1, out, nullptr, nullptr, N_TOK, N_TOK / 64, EMB, 1.0f);
}

// round 15
// speedup vs baseline: 1.0455x; 1.0455x over previous
#include <cuda_runtime.h>
#include <cuda_fp16.h>
#include <math.h>
#include <stdint.h>

#define N_TOK 4096
#define EMB   1024

typedef __half fp16;

// ---------------------------------------------------------------------------
// Device scratch (alloc-free rule: __device__ globals)
// ---------------------------------------------------------------------------
__device__ __align__(256) fp16 gXs0[(size_t)N_TOK * EMB];   // X limbs row-major [4096,1024]
__device__ __align__(256) fp16 gXs1[(size_t)N_TOK * EMB];
__device__ __align__(256) fp16 gXT0[(size_t)EMB * N_TOK];   // X^T limbs [1024,4096]
__device__ __align__(256) fp16 gXT1[(size_t)EMB * N_TOK];
__device__ __align__(256) fp16 gWqs0[(size_t)EMB * EMB];    // Wq limbs row-major
__device__ __align__(256) fp16 gWqs1[(size_t)EMB * EMB];
__device__ __align__(256) fp16 gWks0[(size_t)EMB * EMB];    // Wk limbs row-major
__device__ __align__(256) fp16 gWks1[(size_t)EMB * EMB];
__device__ __align__(256) fp16 gMT0[(size_t)EMB * EMB];     // M^T = Wk Wq^T limbs
__device__ __align__(256) fp16 gMT1[(size_t)EMB * EMB];
__device__ __align__(256) fp16 gT0[(size_t)N_TOK * EMB];    // T = X M limbs
__device__ __align__(256) fp16 gT1[(size_t)N_TOK * EMB];
__device__ __align__(256) float gS[(size_t)N_TOK * N_TOK];  // scaled logits
__device__ __align__(256) fp16 gSh[(size_t)N_TOK * N_TOK];  // softmax probs (1 limb)

// ---------------------------------------------------------------------------
// helpers
// ---------------------------------------------------------------------------
__device__ __forceinline__ uint32_t smem_u32(const void* p) {
    return (uint32_t)__cvta_generic_to_shared(p);
}
__device__ __forceinline__ void cp16(uint32_t dst, const void* src) {
    asm volatile("cp.async.cg.shared.global [%0], [%1], 16;" :: "r"(dst), "l"(src));
}
__device__ __forceinline__ void cp_commit() { asm volatile("cp.async.commit_group;" ::: "memory"); }
__device__ __forceinline__ void cp_wait1()  { asm volatile("cp.async.wait_group 1;" ::: "memory"); }

__device__ __forceinline__ void ldsm_x4(uint32_t* r, uint32_t addr) {
    asm volatile("ldmatrix.sync.aligned.m8n8.x4.shared.b16 {%0,%1,%2,%3}, [%4];"
                 : "=r"(r[0]), "=r"(r[1]), "=r"(r[2]), "=r"(r[3]) : "r"(addr));
}

__device__ __forceinline__ void mma16816(float* d, const uint32_t* a, const uint32_t* b) {
    asm volatile(
        "mma.sync.aligned.m16n8k16.row.col.f32.f16.f16.f32 "
        "{%0,%1,%2,%3}, {%4,%5,%6,%7}, {%8,%9}, {%0,%1,%2,%3};"
        : "+f"(d[0]), "+f"(d[1]), "+f"(d[2]), "+f"(d[3])
        : "r"(a[0]), "r"(a[1]), "r"(a[2]), "r"(a[3]), "r"(b[0]), "r"(b[1]));
}

// fp16-accumulator variant (cross terms only; D = 2 x .f16x2 regs)
__device__ __forceinline__ void mma16816_f16(uint32_t* d, const uint32_t* a, const uint32_t* b) {
    asm volatile(
        "mma.sync.aligned.m16n8k16.row.col.f16.f16.f16.f16 "
        "{%0,%1}, {%2,%3,%4,%5}, {%6,%7}, {%0,%1};"
        : "+r"(d[0]), "+r"(d[1])
        : "r"(a[0]), "r"(a[1]), "r"(a[2]), "r"(a[3]), "r"(b[0]), "r"(b[1]));
}

__device__ __forceinline__ void split2(float v, fp16& h, fp16& l) {
    h = __float2half_rn(v);
    l = __float2half_rn(v - __half2float(h));
}

// swizzled addr inside a 128row x 128B tile: row r, 16B-chunk c (0..7)
__device__ __forceinline__ uint32_t sw_addr(uint32_t base, int r, int c) {
    return base + r * 128 + (((uint32_t)(c ^ (r & 7))) << 4);
}

// ---------------------------------------------------------------------------
// Tile loader: NL limbs, 128 rows x 64 fp16 (128B rows, swizzled), 16KB each
// ---------------------------------------------------------------------------
template <int NL>
__device__ __forceinline__ void load_tiles(const fp16* p0, const fp16* p1,
                                           uint32_t base, int row0, int K, int k0, int tid)
{
    const fp16* ps[2] = { p0, p1 };
#pragma unroll
    for (int s = 0; s < NL; s++) {
#pragma unroll
        for (int i = 0; i < 4; i++) {
            int idx = i * 256 + tid;         // 0..1023
            int r = idx >> 3;                // row 0..127
            int c = idx & 7;                 // 16B chunk 0..7
            const fp16* src = ps[s] + (size_t)(row0 + r) * K + k0 + c * 8;
            cp16(sw_addr(base + s * 16384, r, c), src);
        }
    }
}

// ---------------------------------------------------------------------------
// fp16 limb-product split-GEMM. 3-stage buffer, ONE sync per K-iter,
// R6 intra-iteration ordering (wait -> sync -> compute -> loads -> commit).
// Safety: loads for it+2 target stage (it+2)%3 == (it-1)%3, whose last
// readers (compute of it-1) all passed the top-of-it barrier.
// Products: A0.B0 (fp32) [always]; A0.B1 [NPROD>=2]; A1.B0 [NPROD==3]
//   (cross products use shared fp16 acc if CROSS16).
// CTA tile 128x128, KC=64. 8 warps: warp_m = wid&1 (64 rows), warp_n = wid>>1.
// EPI 0: fp32 store to Cf.  EPI 1: 2-limb fp16 split store to C0/C1.
// ---------------------------------------------------------------------------
template <int NLA, int NLB, int NPROD, int CROSS16, int EPI>
__global__ __launch_bounds__(256, 1)
void hgemm_kernel(const fp16* __restrict__ A0, const fp16* __restrict__ A1,
                  const fp16* __restrict__ B0, const fp16* __restrict__ B1,
                  float* __restrict__ Cf, fp16* __restrict__ C0, fp16* __restrict__ C1,
                  int K, int KITERS, int ldc, float alpha)
{
    constexpr int STAGE_BYTES = (NLA + NLB) * 16384;
    extern __shared__ char smem[];
    const uint32_t SBASE = smem_u32(smem);   // 3 stages x (NLA+NLB) x 16KB

    const int tid = threadIdx.x;
    const int wid = tid >> 5;
    const int lid = tid & 31;
    const int m0 = blockIdx.y * 128;
    const int n0 = blockIdx.x * 128;
    const int m0w = (wid & 1) * 64;
    const int n0w = (wid >> 1) * 32;

    float acc[4][4][4];
#pragma unroll
    for (int i = 0; i < 4; i++)
#pragma unroll
        for (int j = 0; j < 4; j++)
#pragma unroll
            for (int k = 0; k < 4; k++) acc[i][j][k] = 0.f;

    uint32_t acc16[4][4][2];
    if (CROSS16) {
#pragma unroll
        for (int i = 0; i < 4; i++)
#pragma unroll
            for (int j = 0; j < 4; j++) { acc16[i][j][0] = 0u; acc16[i][j][1] = 0u; }
    }

    const int sel = lid >> 3;
    const int lrow = lid & 7;
    const int a_rb = (sel & 1) * 8;   // A x4: M0=(r0,k0) M1=(r1,k0) M2=(r0,k1) M3=(r1,k1)
    const int a_kb = sel >> 1;
    const int b_nb = (sel >> 1) * 8;  // B x4: M0=(n0,k0) M1=(n0,k1) M2=(n1,k0) M3=(n1,k1)
    const int b_kb = sel & 1;

    // prologue: stages 0,1
    load_tiles<NLA>(A0, A1, SBASE, m0, K, 0, tid);
    load_tiles<NLB>(B0, B1, SBASE + NLA * 16384, n0, K, 0, tid);
    cp_commit();
    load_tiles<NLA>(A0, A1, SBASE + STAGE_BYTES, m0, K, 64, tid);
    load_tiles<NLB>(B0, B1, SBASE + STAGE_BYTES + NLA * 16384, n0, K, 64, tid);
    cp_commit();

    int stage = 0;       // it % 3
    int lstage = 2;      // (it+2) % 3
    for (int it = 0; it < KITERS; it++) {
        cp_wait1();
        __syncthreads();

        const uint32_t abase_st = SBASE + stage * STAGE_BYTES;
        const uint32_t bbase_st = abase_st + NLA * 16384;

#pragma unroll
        for (int ks = 0; ks < 4; ks++) {
            // A0 fragments
            uint32_t afr0[4][4];
#pragma unroll
            for (int mt = 0; mt < 4; mt++)
                ldsm_x4(afr0[mt], sw_addr(abase_st, m0w + mt * 16 + a_rb + lrow, ks * 2 + a_kb));
            // B0 fragments
            uint32_t bfr0[2][4];
#pragma unroll
            for (int j = 0; j < 2; j++)
                ldsm_x4(bfr0[j], sw_addr(bbase_st, n0w + j * 16 + b_nb + lrow, ks * 2 + b_kb));
            // main product A0.B0 -> fp32
#pragma unroll
            for (int mt = 0; mt < 4; mt++)
#pragma unroll
                for (int nt = 0; nt < 4; nt++)
                    mma16816(acc[mt][nt], afr0[mt], &bfr0[nt >> 1][(nt & 1) * 2]);

            if (NPROD >= 2) {
                // B1 fragments; A0 still live
                uint32_t bfr1[2][4];
#pragma unroll
                for (int j = 0; j < 2; j++)
                    ldsm_x4(bfr1[j], sw_addr(bbase_st + 16384, n0w + j * 16 + b_nb + lrow, ks * 2 + b_kb));
                if (CROSS16) {
#pragma unroll
                    for (int mt = 0; mt < 4; mt++)
#pragma unroll
                        for (int nt = 0; nt < 4; nt++)
                            mma16816_f16(acc16[mt][nt], afr0[mt], &bfr1[nt >> 1][(nt & 1) * 2]);
                } else {
#pragma unroll
                    for (int mt = 0; mt < 4; mt++)
#pragma unroll
                        for (int nt = 0; nt < 4; nt++)
                            mma16816(acc[mt][nt], afr0[mt], &bfr1[nt >> 1][(nt & 1) * 2]);
                }
            }

            if (NPROD == 3) {
                // A1 fragments; B0 still live
                uint32_t afr1[4][4];
#pragma unroll
                for (int mt = 0; mt < 4; mt++)
                    ldsm_x4(afr1[mt], sw_addr(abase_st + 16384, m0w + mt * 16 + a_rb + lrow, ks * 2 + a_kb));
#pragma unroll
                for (int mt = 0; mt < 4; mt++)
#pragma unroll
                    for (int nt = 0; nt < 4; nt++)
                        mma16816(acc[mt][nt], afr1[mt], &bfr0[nt >> 1][(nt & 1) * 2]);
            }
        }

        // loads for it+2 into stage (it+2)%3 (== (it-1)%3; its readers are done)
        if (it + 2 < KITERS) {
            const uint32_t lbase = SBASE + lstage * STAGE_BYTES;
            load_tiles<NLA>(A0, A1, lbase, m0, K, (it + 2) * 64, tid);
            load_tiles<NLB>(B0, B1, lbase + NLA * 16384, n0, K, (it + 2) * 64, tid);
        }
        cp_commit();

        stage = (stage == 2) ? 0 : stage + 1;
        lstage = (lstage == 2) ? 0 : lstage + 1;
    }

    // epilogue: lane l owns rows gr, gr+8 and col pair (l&3)*2 of each 16x8 frag
    const int gr = lid >> 2;
    const int cp = (lid & 3) * 2;
#pragma unroll
    for (int mt = 0; mt < 4; mt++) {
#pragma unroll
        for (int half = 0; half < 2; half++) {
            const int row = m0 + m0w + mt * 16 + gr + half * 8;
#pragma unroll
            for (int nt = 0; nt < 4; nt++) {
                const int col = n0 + n0w + nt * 8 + cp;
                float v0 = acc[mt][nt][half * 2 + 0];
                float v1 = acc[mt][nt][half * 2 + 1];
                if (CROSS16) {
                    __half2 hc = *(__half2*)&acc16[mt][nt][half];
                    v0 += __low2float(hc);
                    v1 += __high2float(hc);
                }
                v0 *= alpha;
                v1 *= alpha;
                size_t off = (size_t)row * ldc + col;
                if (EPI == 0) {
                    *(float2*)&Cf[off] = make_float2(v0, v1);
                } else {
                    fp16 h0, l0, h1, l1;
                    split2(v0, h0, l0);
                    split2(v1, h1, l1);
                    *(__half2*)&C0[off] = __halves2half2(h0, h1);
                    *(__half2*)&C1[off] = __halves2half2(l0, l1);
                }
            }
        }
    }
}

// ---------------------------------------------------------------------------
// Elementwise 2-limb split
// ---------------------------------------------------------------------------
__global__ __launch_bounds__(256)
void split2_kernel(const float* __restrict__ in, fp16* __restrict__ o0,
                   fp16* __restrict__ o1, int n)
{
    for (int i = blockIdx.x * 256 + threadIdx.x; i < n; i += gridDim.x * 256) {
        fp16 h, l;
        split2(in[i], h, l);
        o0[i] = h; o1[i] = l;
    }
}

// ---------------------------------------------------------------------------
// Transposing 2-limb split: in [R,C] fp32 -> out [C,R] limbs
// ---------------------------------------------------------------------------
__global__ __launch_bounds__(256)
void tsplit2_kernel(const float* __restrict__ in, fp16* __restrict__ o0,
                    fp16* __restrict__ o1, int R, int C)
{
    __shared__ float t[32][33];
    const int cb = blockIdx.x * 32, rb = blockIdx.y * 32;
    const int tx = threadIdx.x & 31, ty = threadIdx.x >> 5;
#pragma unroll
    for (int i = 0; i < 32; i += 8)
        t[ty + i][tx] = in[(size_t)(rb + ty + i) * C + cb + tx];
    __syncthreads();
#pragma unroll
    for (int i = 0; i < 32; i += 8) {
        float v = t[tx][ty + i];
        fp16 h, l;
        split2(v, h, l);
        size_t off = (size_t)(cb + ty + i) * R + rb + tx;
        o0[off] = h;
        o1[off] = l;
    }
}

// ---------------------------------------------------------------------------
// Row softmax of scaled logits -> single fp16 limb (probs are near-one-hot)
// ---------------------------------------------------------------------------
__global__ __launch_bounds__(256)
void softmax_kernel(const float* __restrict__ S, fp16* __restrict__ H)
{
    __shared__ float buf[N_TOK];
    __shared__ float red[256];
    const int row = blockIdx.x;
    const int t = threadIdx.x;
    const float* p = S + (size_t)row * N_TOK;

    float m = -INFINITY;
    for (int i = t; i < N_TOK; i += 256) {
        float v = p[i];
        buf[i] = v;
        m = fmaxf(m, v);
    }
    red[t] = m;
    __syncthreads();
    for (int s = 128; s > 0; s >>= 1) {
        if (t < s) red[t] = fmaxf(red[t], red[t + s]);
        __syncthreads();
    }
    m = red[0];
    __syncthreads();

    float sum = 0.f;
    for (int i = t; i < N_TOK; i += 256) {
        float e = __expf(buf[i] - m);
        buf[i] = e;
        sum += e;
    }
    red[t] = sum;
    __syncthreads();
    for (int s = 128; s > 0; s >>= 1) {
        if (t < s) red[t] += red[t + s];
        __syncthreads();
    }
    const float inv = 1.0f / red[0];
    __syncthreads();

    for (int i = t; i < N_TOK; i += 256)
        H[(size_t)row * N_TOK + i] = __float2half_rn(buf[i] * inv);
}

// ---------------------------------------------------------------------------
extern "C" void kernel_launch(void* const* d_in, const int* in_sizes, int n_in,
                              void* d_out, int out_size)
{
    const float* X  = (const float*)d_in[0];
    const float* Wq = (const float*)d_in[1];
    const float* Wk = (const float*)d_in[2];
    float* out      = (float*)d_out;

    fp16 *xs0, *xs1, *xt0, *xt1, *wq0, *wq1, *wk0, *wk1;
    fp16 *mt0, *mt1, *t0, *t1, *sh;
    float* s;
    cudaGetSymbolAddress((void**)&xs0, gXs0); cudaGetSymbolAddress((void**)&xs1, gXs1);
    cudaGetSymbolAddress((void**)&xt0, gXT0); cudaGetSymbolAddress((void**)&xt1, gXT1);
    cudaGetSymbolAddress((void**)&wq0, gWqs0); cudaGetSymbolAddress((void**)&wq1, gWqs1);
    cudaGetSymbolAddress((void**)&wk0, gWks0); cudaGetSymbolAddress((void**)&wk1, gWks1);
    cudaGetSymbolAddress((void**)&mt0, gMT0); cudaGetSymbolAddress((void**)&mt1, gMT1);
    cudaGetSymbolAddress((void**)&t0, gT0); cudaGetSymbolAddress((void**)&t1, gT1);
    cudaGetSymbolAddress((void**)&s, gS);
    cudaGetSymbolAddress((void**)&sh, gSh);

    const int SM22 = 3 * 4 * 16384;  // 3 stages x (2A + 2B limbs) x 16KB = 192KB
    const int SM12 = 3 * 3 * 16384;  // 3 stages x (1A + 2B limbs) x 16KB = 144KB
    cudaFuncSetAttribute(hgemm_kernel<2,2,3,0,0>, cudaFuncAttributeMaxDynamicSharedMemorySize, SM22);
    cudaFuncSetAttribute(hgemm_kernel<2,2,3,0,1>, cudaFuncAttributeMaxDynamicSharedMemorySize, SM22);
    cudaFuncSetAttribute(hgemm_kernel<1,2,2,1,0>, cudaFuncAttributeMaxDynamicSharedMemorySize, SM12);

    // 1) input splits
    split2_kernel<<<2048, 256>>>(X, xs0, xs1, N_TOK * EMB);
    split2_kernel<<<512, 256>>>(Wq, wq0, wq1, EMB * EMB);
    split2_kernel<<<512, 256>>>(Wk, wk0, wk1, EMB * EMB);
    tsplit2_kernel<<<dim3(EMB / 32, N_TOK / 32), 256>>>(X, xt0, xt1, N_TOK, EMB);

    // 2) M^T = Wk @ Wq^T  (split output; fp32 accum)
    hgemm_kernel<2,2,3,0,1><<<dim3(EMB / 128, EMB / 128), 256, SM22>>>(
        wk0, wk1, wq0, wq1, nullptr, mt0, mt1, EMB, EMB / 64, EMB, 1.0f);

    // 3) T = X @ M  (B = M^T row-major; split output; fp32 accum)
    hgemm_kernel<2,2,3,0,1><<<dim3(EMB / 128, N_TOK / 128), 256, SM22>>>(
        xs0, xs1, mt0, mt1, nullptr, t0, t1, EMB, EMB / 64, EMB, 1.0f);

    // 4) scaled logits = (T @ X^T) / 32  (all products fp32 accum)
    hgemm_kernel<2,2,3,0,0><<<dim3(N_TOK / 128, N_TOK / 128), 256, SM22>>>(
        t0, t1, xs0, xs1, s, nullptr, nullptr, EMB, EMB / 64, N_TOK, 1.0f / 32.0f);

    // 5) softmax rows -> single fp16 limb
    softmax_kernel<<<N_TOK, 256>>>(s, sh);

    // 6) out = S @ X  (A = Sh 1 limb; B = X^T limbs; main fp32 + cross fp16-accum)
    hgemm_kernel<1,2,2,1,0><<<dim3(EMB / 128, N_TOK / 128), 256, SM12>>>(
        sh, nullptr, xt0, xt1, out, nullptr, nullptr, N_TOK, N_TOK / 64, EMB, 1.0f);
}